// round 3
// baseline (speedup 1.0000x reference)
#include <cuda_runtime.h>

#define THREADS 256
#define BUF_CAP 4096
#define MAX_B   4096

// Per-row loss scratch (no cudaMalloc allowed).
__device__ float g_row_loss[MAX_B];

// Order-preserving float<->uint transforms (exact fallback path only; must
// handle negative floats).
__device__ __forceinline__ unsigned f2ord(unsigned b) {
    return (b & 0x80000000u) ? ~b : (b | 0x80000000u);
}
__device__ __forceinline__ unsigned ord2f(unsigned k) {
    return (k & 0x80000000u) ? (k ^ 0x80000000u) : ~k;
}

// One block per row.
// Fast path: single coalesced read of the row; stash values > CUT into SMEM
// (expected ~750 for N(0,1) data with K=327), exact 8-bit radix select of the
// K-th largest among them, then a closed-form loss from threshold/max/exp-sum.
// Fallback (candidate undercount/overflow): exact 4-pass radix select over the
// global row (L2-resident after pass 1), data-independent and unconditional.
__global__ __launch_bounds__(THREADS)
void mmcl_rows(const float* __restrict__ logits,
               const int*   __restrict__ tgt_words,
               int N, int K)
{
    const int row = blockIdx.x;
    const int tid = threadIdx.x;
    const float* __restrict__ x = logits + (size_t)row * N;

    __shared__ float    cand[BUF_CAP];
    __shared__ unsigned hist[256];
    __shared__ int      s_cnt, s_bin, s_above;
    __shared__ float    s_pos;
    __shared__ float    red_s[THREADS / 32];
    __shared__ float    red_m[THREADS / 32];
    __shared__ int      red_g[THREADS / 32];

    // Sniff targets dtype. int64 little-endian with values < 2^31 has zero
    // high words at odd word indices; int32 random targets make this
    // astronomically unlikely (2^-60). All sniff reads are in-bounds for
    // either layout (buffer holds >= 8 words for B >= 8 / B >= 4).
    const bool is64 = (tgt_words[1] == 0 && tgt_words[3] == 0 &&
                       tgt_words[5] == 0 && tgt_words[7] == 0);
    int tgt = is64 ? tgt_words[2 * row] : tgt_words[row];
    tgt = min(max(tgt, 0), N - 1);   // hard guard: never OOB

    if (tid == 0) { s_cnt = 0; s_pos = x[tgt]; }
    __syncthreads();

    // ---- Pass 1: single coalesced read, stash candidates > CUT ----
    const float CUT = 2.0f;
    const int n4 = N >> 2;
    const float4* __restrict__ x4 = (const float4*)x;
    for (int i = tid; i < n4; i += THREADS) {
        float4 v = x4[i];
        int base = i << 2;
        float vv[4] = {v.x, v.y, v.z, v.w};
        #pragma unroll
        for (int j = 0; j < 4; ++j) {
            int idx = base + j;
            if (vv[j] > CUT && idx != tgt) {
                int p = atomicAdd(&s_cnt, 1);
                if (p < BUF_CAP) cand[p] = vv[j];
            }
        }
    }
    __syncthreads();

    const int  cnt  = s_cnt;
    const bool fast = (cnt >= K) && (cnt <= BUF_CAP);

    // ---- Exact radix select of the K-th largest negative ----
    unsigned prefix = 0;
    int kk = K;
    float t;
    if (fast) {
        // All candidates > 2.0 > 0: raw float bits are already order-preserving.
        for (int shift = 24; shift >= 0; shift -= 8) {
            for (int b = tid; b < 256; b += THREADS) hist[b] = 0;
            __syncthreads();
            unsigned hi_mask = (shift == 24) ? 0u : (0xFFFFFFFFu << (shift + 8));
            for (int i = tid; i < cnt; i += THREADS) {
                unsigned key = __float_as_uint(cand[i]);
                if ((key & hi_mask) == prefix)
                    atomicAdd(&hist[(key >> shift) & 255u], 1u);
            }
            __syncthreads();
            if (tid == 0) {
                int acc = 0, b = 255;
                for (; b > 0; --b) {
                    int h = (int)hist[b];
                    if (acc + h >= kk) break;
                    acc += h;
                }
                s_bin = b; s_above = acc;
            }
            __syncthreads();
            prefix |= ((unsigned)s_bin) << shift;
            kk -= s_above;
            __syncthreads();
        }
        t = __uint_as_float(prefix);
    } else {
        for (int shift = 24; shift >= 0; shift -= 8) {
            for (int b = tid; b < 256; b += THREADS) hist[b] = 0;
            __syncthreads();
            unsigned hi_mask = (shift == 24) ? 0u : (0xFFFFFFFFu << (shift + 8));
            for (int i = tid; i < N; i += THREADS) {
                if (i == tgt) continue;
                unsigned key = f2ord(__float_as_uint(x[i]));
                if ((key & hi_mask) == prefix)
                    atomicAdd(&hist[(key >> shift) & 255u], 1u);
            }
            __syncthreads();
            if (tid == 0) {
                int acc = 0, b = 255;
                for (; b > 0; --b) {
                    int h = (int)hist[b];
                    if (acc + h >= kk) break;
                    acc += h;
                }
                s_bin = b; s_above = acc;
            }
            __syncthreads();
            prefix |= ((unsigned)s_bin) << shift;
            kk -= s_above;
            __syncthreads();
        }
        t = __uint_as_float(ord2f(prefix));
    }

    // ---- Final: cnt_gt (# > t), max negative, exp-sum over values > t ----
    float lsum = 0.f, lmax = -1e30f; int lgt = 0;
    if (fast) {
        for (int i = tid; i < cnt; i += THREADS) {
            float v = cand[i];
            if (v > t) { lgt++; lsum += __expf(10.f * (v - t)); lmax = fmaxf(lmax, v); }
        }
    } else {
        for (int i = tid; i < N; i += THREADS) {
            if (i == tgt) continue;
            float v = x[i];
            if (v > t) { lgt++; lsum += __expf(10.f * (v - t)); lmax = fmaxf(lmax, v); }
        }
    }
    // warp reduce
    #pragma unroll
    for (int o = 16; o > 0; o >>= 1) {
        lsum += __shfl_down_sync(0xFFFFFFFFu, lsum, o);
        lmax  = fmaxf(lmax, __shfl_down_sync(0xFFFFFFFFu, lmax, o));
        lgt  += __shfl_down_sync(0xFFFFFFFFu, lgt, o);
    }
    if ((tid & 31) == 0) {
        red_s[tid >> 5] = lsum; red_m[tid >> 5] = lmax; red_g[tid >> 5] = lgt;
    }
    __syncthreads();
    if (tid == 0) {
        float fs = 0.f, fm = -1e30f; int fg = 0;
        #pragma unroll
        for (int w = 0; w < THREADS / 32; ++w) {
            fs += red_s[w]; fm = fmaxf(fm, red_m[w]); fg += red_g[w];
        }
        float pos    = s_pos;
        float m1     = (fg > 0) ? fm : t;   // largest (hardest) negative
        // kept negatives = {v > t} + (K - fg) copies of t, minus one copy of
        // m1 (drop hardest); plus the positive. All scaled by exp(-10t).
        float sum = fs
                  + (float)(K - fg)
                  - __expf(10.f * (m1 - t))
                  + __expf(10.f * (pos - t));
        g_row_loss[row] = __logf(sum) + 10.f * t - 10.f * pos;
    }
}

// Deterministic tree reduction of per-row losses -> mean.
__global__ void mmcl_reduce(float* __restrict__ out, int B)
{
    __shared__ float sh[THREADS];
    int tid = threadIdx.x;
    float s = 0.f;
    for (int i = tid; i < B; i += THREADS) s += g_row_loss[i];
    sh[tid] = s;
    __syncthreads();
    for (int k = THREADS / 2; k > 0; k >>= 1) {
        if (tid < k) sh[tid] += sh[tid + k];
        __syncthreads();
    }
    if (tid == 0) out[0] = sh[0] / (float)B;
}

extern "C" void kernel_launch(void* const* d_in, const int* in_sizes, int n_in,
                              void* d_out, int out_size)
{
    const float* logits    = (const float*)d_in[0];
    const int*   tgt_words = (const int*)d_in[1];
    int B = in_sizes[1];
    int N = in_sizes[0] / B;
    int K = (int)(0.01 * (double)(N - 1));   // matches python int(r*(N-1))
    mmcl_rows<<<B, THREADS>>>(logits, tgt_words, N, K);
    mmcl_reduce<<<1, THREADS>>>((float*)d_out, B);
}

// round 6
// speedup vs baseline: 1.0837x; 1.0837x over previous
#include <cuda_runtime.h>

#define THREADS 256
#define UNROLL  8
#define BUF_CAP 2048
#define MAX_B   8192

// Per-row loss scratch (no cudaMalloc allowed).
__device__ float g_row_loss[MAX_B];

// Order-preserving float<->uint transforms (exact fallback path only).
__device__ __forceinline__ unsigned f2ord(unsigned b) {
    return (b & 0x80000000u) ? ~b : (b | 0x80000000u);
}
__device__ __forceinline__ unsigned ord2f(unsigned k) {
    return (k & 0x80000000u) ? (k ^ 0x80000000u) : ~k;
}

// One block per row.
// Fast path: single coalesced batched read of the row; warp-aggregated
// compaction of values > CUT into SMEM (expected ~750 for N(0,1), K=327),
// exact 8-bit radix select of the K-th largest among them, closed-form loss.
// Fallback: exact data-independent radix select over the global row.
__global__ __launch_bounds__(THREADS)
void mmcl_rows(const float* __restrict__ logits,
               const int*   __restrict__ tgt_words,
               int N, int K)
{
    const int row  = blockIdx.x;
    const int tid  = threadIdx.x;
    const int lane = tid & 31;
    const float* __restrict__ x = logits + (size_t)row * N;

    __shared__ float    cand[BUF_CAP];
    __shared__ unsigned hist[256];
    __shared__ unsigned scn[256];
    __shared__ int      s_cnt, s_bin, s_above;
    __shared__ float    s_pos;
    __shared__ float    red_s[THREADS / 32];
    __shared__ float    red_m[THREADS / 32];
    __shared__ int      red_g[THREADS / 32];

    // Sniff targets dtype (int64 vs int32 word layout). All reads in-bounds
    // for either layout; false positive odds ~2^-60 for int32 targets.
    const bool is64 = (tgt_words[1] == 0 && tgt_words[3] == 0 &&
                       tgt_words[5] == 0 && tgt_words[7] == 0);
    int tgt = is64 ? tgt_words[2 * row] : tgt_words[row];
    tgt = min(max(tgt, 0), N - 1);   // hard guard: never OOB

    if (tid == 0) { s_cnt = 0; s_pos = x[tgt]; }
    __syncthreads();

    // ---- Pass 1: batched read (8 outstanding LDG.128 per thread), then
    //      warp-aggregated compaction of candidates > CUT ----
    const float CUT = 2.0f;
    const int n4 = N >> 2;
    const int TILE = THREADS * UNROLL;
    const int n_full = (n4 / TILE) * TILE;
    const float4* __restrict__ x4 = (const float4*)x;

    for (int i0 = 0; i0 < n_full; i0 += TILE) {
        float4 v[UNROLL];
        #pragma unroll
        for (int u = 0; u < UNROLL; ++u)
            v[u] = x4[i0 + u * THREADS + tid];
        #pragma unroll
        for (int u = 0; u < UNROLL; ++u) {
            int base_idx = (i0 + u * THREADS + tid) << 2;
            float vv[4] = {v[u].x, v[u].y, v[u].z, v[u].w};
            bool pr[4];
            #pragma unroll
            for (int j = 0; j < 4; ++j)
                pr[j] = (vv[j] > CUT) && (base_idx + j != tgt);
            #pragma unroll
            for (int j = 0; j < 4; ++j) {
                unsigned m = __ballot_sync(0xFFFFFFFFu, pr[j]);
                if (m) {
                    int leader = __ffs(m) - 1;
                    int base = 0;
                    if (lane == leader) base = atomicAdd(&s_cnt, __popc(m));
                    base = __shfl_sync(0xFFFFFFFFu, base, leader);
                    if (pr[j]) {
                        int p = base + __popc(m & ((1u << lane) - 1u));
                        if (p < BUF_CAP) cand[p] = vv[j];
                    }
                }
            }
        }
    }
    // generic remainder (vec4 part beyond full tiles, then scalar tail)
    for (int i = n_full + tid; i < n4; i += THREADS) {
        float4 v = x4[i];
        int base_idx = i << 2;
        float vv[4] = {v.x, v.y, v.z, v.w};
        #pragma unroll
        for (int j = 0; j < 4; ++j) {
            if (vv[j] > CUT && base_idx + j != tgt) {
                int p = atomicAdd(&s_cnt, 1);
                if (p < BUF_CAP) cand[p] = vv[j];
            }
        }
    }
    for (int i = (n4 << 2) + tid; i < N; i += THREADS) {
        float vv = x[i];
        if (vv > CUT && i != tgt) {
            int p = atomicAdd(&s_cnt, 1);
            if (p < BUF_CAP) cand[p] = vv;
        }
    }
    __syncthreads();

    const int  cnt  = s_cnt;
    const bool fast = (cnt >= K) && (cnt <= BUF_CAP);

    // ---- Exact radix select of the K-th largest negative ----
    unsigned prefix = 0;
    int kk = K;
    float t;
    #pragma unroll 1
    for (int shift = 24; shift >= 0; shift -= 8) {
        hist[tid] = 0;
        __syncthreads();
        unsigned hi_mask = (shift == 24) ? 0u : (0xFFFFFFFFu << (shift + 8));
        if (fast) {
            // all candidates > 2.0 > 0: raw bits are order-preserving
            for (int i = tid; i < cnt; i += THREADS) {
                unsigned key = __float_as_uint(cand[i]);
                if ((key & hi_mask) == prefix)
                    atomicAdd(&hist[(key >> shift) & 255u], 1u);
            }
        } else {
            for (int i = tid; i < N; i += THREADS) {
                if (i == tgt) continue;
                unsigned key = f2ord(__float_as_uint(x[i]));
                if ((key & hi_mask) == prefix)
                    atomicAdd(&hist[(key >> shift) & 255u], 1u);
            }
        }
        __syncthreads();
        // parallel suffix sum over 256 bins (Hillis-Steele, 8 steps)
        unsigned* src = hist;
        unsigned* dst = scn;
        #pragma unroll
        for (int d = 1; d < 256; d <<= 1) {
            dst[tid] = src[tid] + ((tid + d < 256) ? src[tid + d] : 0u);
            __syncthreads();
            unsigned* tmp = src; src = dst; dst = tmp;
        }
        // suffix[b] = src[b]; pick b with suffix[b+1] < kk <= suffix[b]
        unsigned above = (tid < 255) ? src[tid + 1] : 0u;
        if ((int)src[tid] >= kk && (int)above < kk) {
            s_bin = tid; s_above = (int)above;
        }
        __syncthreads();
        prefix |= ((unsigned)s_bin) << shift;
        kk -= s_above;
        __syncthreads();
    }
    t = fast ? __uint_as_float(prefix) : __uint_as_float(ord2f(prefix));

    // ---- Final: cnt_gt (# > t), max negative, exp-sum over values > t ----
    float lsum = 0.f, lmax = -1e30f; int lgt = 0;
    if (fast) {
        for (int i = tid; i < cnt; i += THREADS) {
            float v = cand[i];
            if (v > t) { lgt++; lsum += __expf(10.f * (v - t)); lmax = fmaxf(lmax, v); }
        }
    } else {
        for (int i = tid; i < N; i += THREADS) {
            if (i == tgt) continue;
            float v = x[i];
            if (v > t) { lgt++; lsum += __expf(10.f * (v - t)); lmax = fmaxf(lmax, v); }
        }
    }
    #pragma unroll
    for (int o = 16; o > 0; o >>= 1) {
        lsum += __shfl_down_sync(0xFFFFFFFFu, lsum, o);
        lmax  = fmaxf(lmax, __shfl_down_sync(0xFFFFFFFFu, lmax, o));
        lgt  += __shfl_down_sync(0xFFFFFFFFu, lgt, o);
    }
    if (lane == 0) {
        red_s[tid >> 5] = lsum; red_m[tid >> 5] = lmax; red_g[tid >> 5] = lgt;
    }
    __syncthreads();
    if (tid == 0) {
        float fs = 0.f, fm = -1e30f; int fg = 0;
        #pragma unroll
        for (int w = 0; w < THREADS / 32; ++w) {
            fs += red_s[w]; fm = fmaxf(fm, red_m[w]); fg += red_g[w];
        }
        float pos = s_pos;
        float m1  = (fg > 0) ? fm : t;   // hardest negative
        // kept negatives = {v > t} + (K - fg) copies of t, minus the hardest
        // (m1); plus the positive. All scaled by exp(-10t).
        float sum = fs
                  + (float)(K - fg)
                  - __expf(10.f * (m1 - t))
                  + __expf(10.f * (pos - t));
        g_row_loss[row] = __logf(sum) + 10.f * t - 10.f * pos;
    }
}

// Deterministic tree reduction of per-row losses -> mean.
__global__ void mmcl_reduce(float* __restrict__ out, int B)
{
    __shared__ float sh[THREADS];
    int tid = threadIdx.x;
    float s = 0.f;
    for (int i = tid; i < B; i += THREADS) s += g_row_loss[i];
    sh[tid] = s;
    __syncthreads();
    for (int k = THREADS / 2; k > 0; k >>= 1) {
        if (tid < k) sh[tid] += sh[tid + k];
        __syncthreads();
    }
    if (tid == 0) out[0] = sh[0] / (float)B;
}

extern "C" void kernel_launch(void* const* d_in, const int* in_sizes, int n_in,
                              void* d_out, int out_size)
{
    const float* logits    = (const float*)d_in[0];
    const int*   tgt_words = (const int*)d_in[1];
    int B = in_sizes[1];
    int N = in_sizes[0] / B;
    int K = (int)(0.01 * (double)(N - 1));   // matches python int(r*(N-1))
    mmcl_rows<<<B, THREADS>>>(logits, tgt_words, N, K);
    mmcl_reduce<<<1, THREADS>>>((float*)d_out, B);
}